// round 7
// baseline (speedup 1.0000x reference)
#include <cuda_runtime.h>
#include <math.h>

#define N0 4096
#define F0 512
#define H  256
#define KP1 3072
#define KP2 2304
#define KP3 1728

// ---------------- device scratch (static globals: no runtime allocation) ----------------
__device__ __align__(256) float g_feat[N0 * F0];
__device__ __align__(256) float g_A [(size_t)N0 * N0];
__device__ __align__(256) float g_A2[(size_t)N0 * N0];
__device__ __align__(256) float g_x [N0 * H];
__device__ __align__(256) float g_x2[N0 * H];
__device__ __align__(256) float g_y [N0 * H];
__device__ float g_sq[N0];
__device__ float g_dis[N0];
__device__ float g_u[N0];
__device__ float g_v[N0];
__device__ float g_score[N0];
__device__ int   g_perm[N0];
__device__ float g_vals[N0];
__device__ int   g_maxint;
__device__ float g_part[32 * 512];

// ---------------- init ----------------
__global__ void k_init(float* out) {
    int t = blockIdx.x * blockDim.x + threadIdx.x;
    if (t < 512) out[t] = 0.0f;
    if (t == 0) g_maxint = 0;
}

// ---------------- pos MLP + concat -> feat [N0, 512] ----------------
__global__ void k_posconcat(const float* __restrict__ feature,
                            const float* __restrict__ img,
                            const float* __restrict__ Wp,
                            const float* __restrict__ bp) {
    int n = blockIdx.x;
    int t = threadIdx.x;  // 128 threads
    const float* fr = feature + (size_t)n * 500;
    float* dst = g_feat + (size_t)n * F0;
    for (int i = t; i < 500; i += 128) dst[i] = fr[i];
    if (t < 12) {
        float s = bp[t];
#pragma unroll
        for (int h = 0; h < 6; h++) s += img[n * 6 + h] * Wp[h * 12 + t];
        dst[500 + t] = fmaxf(s, 0.0f);
    }
}

// ---------------- SGEMM: C[M,N] = A[M,K] @ B (BT: B is [N,K] row-major) ----------------
// EPI 0: plain store
// EPI 1: C = dis[m] * acc                         (y = dis .* (x@W))
// EPI 2: C = relu(dis[m]*(acc + ybuf[m,n]) + bias[n])   (GCN with self loop)
// LOWER: skip blocks above diagonal (Gram lower triangle only)
// TRI:   A operand strictly lower triangular -> K loop limited to m0+128
template<int EPI, bool BT, bool LOWER, bool TRI>
__global__ __launch_bounds__(256) void k_sgemm(
    const float* __restrict__ A, const float* __restrict__ B, float* __restrict__ C,
    int M, int N, int K,
    const float* __restrict__ dis, const float* __restrict__ ybuf,
    const float* __restrict__ bias)
{
    int bx = blockIdx.x, by = blockIdx.y;
    if (LOWER && bx > by) return;
    int m0 = by * 128, n0 = bx * 128;
    int Kend = TRI ? min(K, m0 + 128) : K;

    __shared__ float As[8][128];
    __shared__ float Bs[8][128];

    int tid = threadIdx.x;
    int trow = tid >> 4, tcol = tid & 15;
    float acc[8][8];
#pragma unroll
    for (int i = 0; i < 8; i++)
#pragma unroll
        for (int j = 0; j < 8; j++) acc[i][j] = 0.0f;

    int ar = tid >> 1, ac = (tid & 1) * 4;
    int brn = tid >> 5, bcn = (tid & 31) * 4;

    for (int k0 = 0; k0 < Kend; k0 += 8) {
        float4 av = *(const float4*)(A + (size_t)(m0 + ar) * K + k0 + ac);
        As[ac + 0][ar] = av.x; As[ac + 1][ar] = av.y;
        As[ac + 2][ar] = av.z; As[ac + 3][ar] = av.w;
        if (!BT) {
            float4 bv = *(const float4*)(B + (size_t)(k0 + brn) * N + n0 + bcn);
            *(float4*)&Bs[brn][bcn] = bv;
        } else {
            float4 bv = *(const float4*)(B + (size_t)(n0 + ar) * K + k0 + ac);
            Bs[ac + 0][ar] = bv.x; Bs[ac + 1][ar] = bv.y;
            Bs[ac + 2][ar] = bv.z; Bs[ac + 3][ar] = bv.w;
        }
        __syncthreads();
#pragma unroll
        for (int kk = 0; kk < 8; kk++) {
            float ra[8], rb[8];
#pragma unroll
            for (int i = 0; i < 8; i++) ra[i] = As[kk][trow * 8 + i];
#pragma unroll
            for (int j = 0; j < 8; j++) rb[j] = Bs[kk][tcol * 8 + j];
#pragma unroll
            for (int i = 0; i < 8; i++)
#pragma unroll
                for (int j = 0; j < 8; j++)
                    acc[i][j] = fmaf(ra[i], rb[j], acc[i][j]);
        }
        __syncthreads();
    }

#pragma unroll
    for (int i = 0; i < 8; i++) {
        int m = m0 + trow * 8 + i;
        float d = (EPI >= 1) ? dis[m] : 0.0f;
#pragma unroll
        for (int j = 0; j < 8; j++) {
            int n = n0 + tcol * 8 + j;
            float v = acc[i][j];
            if (EPI == 1) v = d * v;
            else if (EPI == 2) {
                v = d * (v + ybuf[(size_t)m * N + n]) + bias[n];
                v = fmaxf(v, 0.0f);
            }
            C[(size_t)m * N + n] = v;
        }
    }
}

// ---------------- diag of Gram = ||x||^2 ----------------
__global__ void k_diag() {
    int i = blockIdx.x * blockDim.x + threadIdx.x;
    if (i < N0) g_sq[i] = g_A[(size_t)i * N0 + i];
}

// ---------------- max d2 over lower triangle ----------------
__global__ void k_maxd2() {
    int j = blockIdx.x, t = threadIdx.x;
    float sj = g_sq[j];
    const float* row = g_A + (size_t)j * N0;
    float m = 0.0f;
    for (int i = t; i <= j; i += 256) {
        float d2 = sj + g_sq[i] - 2.0f * row[i];
        m = fmaxf(m, d2);
    }
    __shared__ float sm[256];
    sm[t] = m; __syncthreads();
    for (int s = 128; s > 0; s >>= 1) {
        if (t < s) sm[t] = fmaxf(sm[t], sm[t + s]);
        __syncthreads();
    }
    if (t == 0) atomicMax(&g_maxint, __float_as_int(fmaxf(sm[0], 0.0f)));
}

// ---------------- build adjacency in place + degree -> dis ----------------
__global__ void k_buildadj() {
    int j = blockIdx.x, t = threadIdx.x;
    float thr = 0.5f * __int_as_float(g_maxint);
    float sj = g_sq[j];
    float* row = g_A + (size_t)j * N0;
    float cnt = 0.0f;
    for (int i = t; i < N0; i += 256) {
        float a = 0.0f;
        if (i < j) {
            float d2 = sj + g_sq[i] - 2.0f * row[i];
            a = (d2 < thr) ? 1.0f : 0.0f;
        }
        row[i] = a;
        cnt += a;
    }
    __shared__ float sm[256];
    sm[t] = cnt; __syncthreads();
    for (int s = 128; s > 0; s >>= 1) {
        if (t < s) sm[t] += sm[t + s];
        __syncthreads();
    }
    if (t == 0) g_dis[j] = rsqrtf(1.0f + sm[0]);
}

// ---------------- scorer matvecs: u = x@Wn, v = x@Wr ----------------
__global__ void k_scorevec(const float* __restrict__ x,
                           const float* __restrict__ Wn,
                           const float* __restrict__ Wr) {
    int j = blockIdx.x, t = threadIdx.x;  // 256 threads
    float p = x[(size_t)j * H + t];
    float uu = p * Wn[t], vv = p * Wr[t];
    __shared__ float su[256], sv[256];
    su[t] = uu; sv[t] = vv; __syncthreads();
    for (int s = 128; s > 0; s >>= 1) {
        if (t < s) { su[t] += su[t + s]; sv[t] += sv[t + s]; }
        __syncthreads();
    }
    if (t == 0) { g_u[j] = su[0]; g_v[j] = sv[0]; }
}

// ---------------- w = A@u (A strictly lower), score = tanh(w + bs + v) ----------------
__global__ void k_auscore(const float* __restrict__ Aadj,
                          const float* __restrict__ bsp, int Nl) {
    int j = blockIdx.x, t = threadIdx.x;
    const float* row = Aadj + (size_t)j * Nl;
    float s = 0.0f;
    for (int i = t; i < j; i += 256) s += row[i] * g_u[i];
    __shared__ float sm[256];
    sm[t] = s; __syncthreads();
    for (int st = 128; st > 0; st >>= 1) {
        if (t < st) sm[t] += sm[t + st];
        __syncthreads();
    }
    if (t == 0) g_score[j] = tanhf(sm[0] + bsp[0] + g_v[j]);
}

// ---------------- top-k via bitonic sort (1 block, 1024 threads, P=4096) ----------------
__device__ void bitonic4096(float* ss, int* si, bool byScore) {
    int t = threadIdx.x;
    for (int size = 2; size <= 4096; size <<= 1) {
        for (int stride = size >> 1; stride > 0; stride >>= 1) {
            __syncthreads();
            for (int p = t; p < 2048; p += 1024) {
                int i = ((p / stride) * (stride << 1)) + (p % stride);
                int j = i + stride;
                bool dirUp = ((i & size) == 0);
                float sa = ss[i], sb = ss[j];
                int ia = si[i], ib = si[j];
                // b true if j-element precedes i-element in target order
                bool b = byScore ? ((sb > sa) || (sb == sa && ib < ia)) : (ib < ia);
                if (b == dirUp) {
                    ss[i] = sb; ss[j] = sa;
                    si[i] = ib; si[j] = ia;
                }
            }
        }
    }
    __syncthreads();
}

__global__ __launch_bounds__(1024) void k_topk(int Nl, int k) {
    __shared__ float ss[4096];
    __shared__ int   si[4096];
    int t = threadIdx.x;
    for (int i = t; i < 4096; i += 1024) {
        if (i < Nl) { ss[i] = g_score[i]; si[i] = i; }
        else        { ss[i] = __int_as_float(0xff800000); si[i] = 0x7FFFFFFF; }
    }
    __syncthreads();
    // phase 1: descending by score (tie -> smaller index), matches lax.top_k set
    bitonic4096(ss, si, true);
    // phase 2: keep first k, re-sort selected by index ascending (keeps A triangular)
    for (int i = t; i < 4096; i += 1024)
        if (i >= k) si[i] = 0x7FFFFFFF;
    __syncthreads();
    bitonic4096(ss, si, false);
    for (int r = t; r < k; r += 1024) { g_perm[r] = si[r]; g_vals[r] = ss[r]; }
}

// ---------------- gather x: xp[r] = x[perm[r]] * vals[r] ----------------
__global__ void k_gatherx(const float* __restrict__ xin, float* __restrict__ xout, int k) {
    int r = blockIdx.x, t = threadIdx.x;
    int pr = g_perm[r];
    float v = g_vals[r];
    xout[(size_t)r * H + t] = xin[(size_t)pr * H + t] * v;
}

// ---------------- gather A (stays strictly lower) + new degrees ----------------
__global__ void k_gatherA(const float* __restrict__ Ain, float* __restrict__ Aout,
                          int Nin, int k) {
    int r = blockIdx.x, t = threadIdx.x;
    int pr = g_perm[r];
    const float* rin = Ain + (size_t)pr * Nin;
    float* rout = Aout + (size_t)r * k;
    float cnt = 0.0f;
    for (int c = t; c < k; c += 256) {
        float a = (c < r) ? rin[g_perm[c]] : 0.0f;
        rout[c] = a;
        cnt += a;
    }
    __shared__ float sm[256];
    sm[t] = cnt; __syncthreads();
    for (int s = 128; s > 0; s >>= 1) {
        if (t < s) sm[t] += sm[t + s];
        __syncthreads();
    }
    if (t == 0) g_dis[r] = rsqrtf(1.0f + sm[0]);
}

// ---------------- readout: column max + sum -> accumulate into out ----------------
__global__ void k_readout_part(const float* __restrict__ x, int k) {
    int b = blockIdx.x, t = threadIdx.x;  // grid 32, 256 threads
    float mx = __int_as_float(0xff800000), sm = 0.0f;
    for (int r = b; r < k; r += 32) {
        float v = x[(size_t)r * H + t];
        mx = fmaxf(mx, v);
        sm += v;
    }
    g_part[b * 512 + t] = mx;
    g_part[b * 512 + 256 + t] = sm;
}

__global__ void k_readout_final(float* out, float invk) {
    int t = threadIdx.x;  // 256
    float mx = __int_as_float(0xff800000), sm = 0.0f;
    for (int b = 0; b < 32; b++) {
        mx = fmaxf(mx, g_part[b * 512 + t]);
        sm += g_part[b * 512 + 256 + t];
    }
    out[t] += mx;
    out[256 + t] += sm * invk;
}

// ---------------- one GCN + SAGPool + readout layer ----------------
static void run_layer(const float* xin, int Kin, const float* Ain, int Nl,
                      const float* W, const float* bvec,
                      const float* Wr, const float* Wn, const float* bs,
                      int k, float* xnew, float* xpool, float* Apool,
                      float* ybuf, const float* pdis, float* d_out)
{
    // y = dis .* (x @ W)
    {
        dim3 g(H / 128, Nl / 128);
        k_sgemm<1, false, false, false><<<g, 256>>>(xin, W, ybuf, Nl, H, Kin,
                                                    pdis, nullptr, nullptr);
    }
    // xnew = relu(dis .* (A@y + y) + b)   [A strictly lower -> TRI K-limit]
    {
        dim3 g(H / 128, Nl / 128);
        k_sgemm<2, false, false, true><<<g, 256>>>(Ain, ybuf, xnew, Nl, H, Nl,
                                                   pdis, ybuf, bvec);
    }
    k_scorevec<<<Nl, 256>>>(xnew, Wn, Wr);
    k_auscore<<<Nl, 256>>>(Ain, bs, Nl);
    k_topk<<<1, 1024>>>(Nl, k);
    k_gatherx<<<k, 256>>>(xnew, xpool, k);
    k_gatherA<<<k, 256>>>(Ain, Apool, Nl, k);
    k_readout_part<<<32, 256>>>(xpool, k);
    k_readout_final<<<1, 256>>>(d_out, 1.0f / (float)k);
}

extern "C" void kernel_launch(void* const* d_in, const int* in_sizes, int n_in,
                              void* d_out, int out_size) {
    const float* feature = (const float*)d_in[0];
    const float* img     = (const float*)d_in[1];
    const float* W_pos   = (const float*)d_in[2];
    const float* b_pos   = (const float*)d_in[3];
    const float* W1 = (const float*)d_in[4];  const float* b1 = (const float*)d_in[5];
    const float* W2 = (const float*)d_in[6];  const float* b2 = (const float*)d_in[7];
    const float* W3 = (const float*)d_in[8];  const float* b3 = (const float*)d_in[9];
    const float* Wr1 = (const float*)d_in[10]; const float* Wn1 = (const float*)d_in[11];
    const float* bs1 = (const float*)d_in[12];
    const float* Wr2 = (const float*)d_in[13]; const float* Wn2 = (const float*)d_in[14];
    const float* bs2 = (const float*)d_in[15];
    const float* Wr3 = (const float*)d_in[16]; const float* Wn3 = (const float*)d_in[17];
    const float* bs3 = (const float*)d_in[18];
    float* out = (float*)d_out;

    float *pfeat, *pA, *pA2, *px, *px2, *py, *pdis;
    cudaGetSymbolAddress((void**)&pfeat, g_feat);
    cudaGetSymbolAddress((void**)&pA,   g_A);
    cudaGetSymbolAddress((void**)&pA2,  g_A2);
    cudaGetSymbolAddress((void**)&px,   g_x);
    cudaGetSymbolAddress((void**)&px2,  g_x2);
    cudaGetSymbolAddress((void**)&py,   g_y);
    cudaGetSymbolAddress((void**)&pdis, g_dis);   // FIX: device address, not host shadow

    k_init<<<2, 256>>>(out);
    k_posconcat<<<N0, 128>>>(feature, img, W_pos, b_pos);

    // Gram (lower triangle + diagonal only): G = feat @ feat^T into g_A
    {
        dim3 g(N0 / 128, N0 / 128);
        k_sgemm<0, true, true, false><<<g, 256>>>(pfeat, pfeat, pA, N0, N0, F0,
                                                  nullptr, nullptr, nullptr);
    }
    k_diag<<<N0 / 256, 256>>>();
    k_maxd2<<<N0, 256>>>();
    k_buildadj<<<N0, 256>>>();

    // layer 1: A in g_A (4096), pool -> x2 (3072), A -> g_A2
    run_layer(pfeat, F0, pA, N0, W1, b1, Wr1, Wn1, bs1, KP1, px, px2, pA2, py, pdis, out);
    // layer 2: A in g_A2 (3072), pool -> x2 (2304), A -> g_A
    run_layer(px2, H, pA2, KP1, W2, b2, Wr2, Wn2, bs2, KP2, px, px2, pA, py, pdis, out);
    // layer 3: A in g_A (2304), pool -> x2 (1728), A -> g_A2
    run_layer(px2, H, pA, KP2, W3, b3, Wr3, Wn3, bs3, KP3, px, px2, pA2, py, pdis, out);
}

// round 8
// speedup vs baseline: 1.0006x; 1.0006x over previous
#include <cuda_runtime.h>
#include <math.h>

#define N0 4096
#define F0 512
#define H  256
#define KP1 3072
#define KP2 2304
#define KP3 1728

// ---------------- device scratch (static globals: no runtime allocation) ----------------
__device__ __align__(256) float g_feat[N0 * F0];
__device__ __align__(256) float g_A [(size_t)N0 * N0];
__device__ __align__(256) float g_A2[(size_t)N0 * N0];
__device__ __align__(256) float g_x [N0 * H];
__device__ __align__(256) float g_x2[N0 * H];
__device__ __align__(256) float g_y [N0 * H];
__device__ float g_sq[N0];
__device__ float g_dis[N0];
__device__ float g_u[N0];
__device__ float g_v[N0];
__device__ float g_score[N0];
__device__ int   g_perm[N0];
__device__ float g_vals[N0];
__device__ int   g_maxint;
__device__ float g_part[32 * 512];

// ---------------- init ----------------
__global__ void k_init(float* out) {
    int t = blockIdx.x * blockDim.x + threadIdx.x;
    if (t < 512) out[t] = 0.0f;
    if (t == 0) g_maxint = 0;
}

// ---------------- pos MLP + concat -> feat [N0, 512] ----------------
__global__ void k_posconcat(const float* __restrict__ feature,
                            const float* __restrict__ img,
                            const float* __restrict__ Wp,
                            const float* __restrict__ bp) {
    int n = blockIdx.x;
    int t = threadIdx.x;  // 128 threads
    const float* fr = feature + (size_t)n * 500;
    float* dst = g_feat + (size_t)n * F0;
    for (int i = t; i < 500; i += 128) dst[i] = fr[i];
    if (t < 12) {
        float s = bp[t];
#pragma unroll
        for (int h = 0; h < 6; h++) s += img[n * 6 + h] * Wp[h * 12 + t];
        dst[500 + t] = fmaxf(s, 0.0f);
    }
}

// ---------------- SGEMM: C[M,N] = A[M,K] @ B (BT: B is [N,K] row-major) ----------------
// EPI 0: plain store
// EPI 1: C = dis[m] * acc                         (y = dis .* (x@W))
// EPI 2: C = relu(dis[m]*(acc + ybuf[m,n]) + bias[n])   (GCN with self loop)
// LOWER: skip blocks above diagonal (Gram lower triangle only)
// TRI:   A operand strictly lower triangular -> K loop limited to m0+128
template<int EPI, bool BT, bool LOWER, bool TRI>
__global__ __launch_bounds__(256) void k_sgemm(
    const float* __restrict__ A, const float* __restrict__ B, float* __restrict__ C,
    int M, int N, int K,
    const float* __restrict__ dis, const float* __restrict__ ybuf,
    const float* __restrict__ bias)
{
    int bx = blockIdx.x, by = blockIdx.y;
    if (LOWER && bx > by) return;
    int m0 = by * 128, n0 = bx * 128;
    int Kend = TRI ? min(K, m0 + 128) : K;

    __shared__ float As[8][128];
    __shared__ float Bs[8][128];

    int tid = threadIdx.x;
    int trow = tid >> 4, tcol = tid & 15;
    float acc[8][8];
#pragma unroll
    for (int i = 0; i < 8; i++)
#pragma unroll
        for (int j = 0; j < 8; j++) acc[i][j] = 0.0f;

    int ar = tid >> 1, ac = (tid & 1) * 4;
    int brn = tid >> 5, bcn = (tid & 31) * 4;

    for (int k0 = 0; k0 < Kend; k0 += 8) {
        float4 av = *(const float4*)(A + (size_t)(m0 + ar) * K + k0 + ac);
        As[ac + 0][ar] = av.x; As[ac + 1][ar] = av.y;
        As[ac + 2][ar] = av.z; As[ac + 3][ar] = av.w;
        if (!BT) {
            float4 bv = *(const float4*)(B + (size_t)(k0 + brn) * N + n0 + bcn);
            *(float4*)&Bs[brn][bcn] = bv;
        } else {
            float4 bv = *(const float4*)(B + (size_t)(n0 + ar) * K + k0 + ac);
            Bs[ac + 0][ar] = bv.x; Bs[ac + 1][ar] = bv.y;
            Bs[ac + 2][ar] = bv.z; Bs[ac + 3][ar] = bv.w;
        }
        __syncthreads();
#pragma unroll
        for (int kk = 0; kk < 8; kk++) {
            float ra[8], rb[8];
#pragma unroll
            for (int i = 0; i < 8; i++) ra[i] = As[kk][trow * 8 + i];
#pragma unroll
            for (int j = 0; j < 8; j++) rb[j] = Bs[kk][tcol * 8 + j];
#pragma unroll
            for (int i = 0; i < 8; i++)
#pragma unroll
                for (int j = 0; j < 8; j++)
                    acc[i][j] = fmaf(ra[i], rb[j], acc[i][j]);
        }
        __syncthreads();
    }

#pragma unroll
    for (int i = 0; i < 8; i++) {
        int m = m0 + trow * 8 + i;
        float d = (EPI >= 1) ? dis[m] : 0.0f;
#pragma unroll
        for (int j = 0; j < 8; j++) {
            int n = n0 + tcol * 8 + j;
            float v = acc[i][j];
            if (EPI == 1) v = d * v;
            else if (EPI == 2) {
                v = d * (v + ybuf[(size_t)m * N + n]) + bias[n];
                v = fmaxf(v, 0.0f);
            }
            C[(size_t)m * N + n] = v;
        }
    }
}

// ---------------- diag of Gram = ||x||^2 ----------------
__global__ void k_diag() {
    int i = blockIdx.x * blockDim.x + threadIdx.x;
    if (i < N0) g_sq[i] = g_A[(size_t)i * N0 + i];
}

// ---------------- max d2 over lower triangle ----------------
__global__ void k_maxd2() {
    int j = blockIdx.x, t = threadIdx.x;
    float sj = g_sq[j];
    const float* row = g_A + (size_t)j * N0;
    float m = 0.0f;
    for (int i = t; i <= j; i += 256) {
        float d2 = sj + g_sq[i] - 2.0f * row[i];
        m = fmaxf(m, d2);
    }
    __shared__ float sm[256];
    sm[t] = m; __syncthreads();
    for (int s = 128; s > 0; s >>= 1) {
        if (t < s) sm[t] = fmaxf(sm[t], sm[t + s]);
        __syncthreads();
    }
    if (t == 0) atomicMax(&g_maxint, __float_as_int(fmaxf(sm[0], 0.0f)));
}

// ---------------- build adjacency in place + degree -> dis ----------------
__global__ void k_buildadj() {
    int j = blockIdx.x, t = threadIdx.x;
    float thr = 0.5f * __int_as_float(g_maxint);
    float sj = g_sq[j];
    float* row = g_A + (size_t)j * N0;
    float cnt = 0.0f;
    for (int i = t; i < N0; i += 256) {
        float a = 0.0f;
        if (i < j) {
            float d2 = sj + g_sq[i] - 2.0f * row[i];
            a = (d2 < thr) ? 1.0f : 0.0f;
        }
        row[i] = a;
        cnt += a;
    }
    __shared__ float sm[256];
    sm[t] = cnt; __syncthreads();
    for (int s = 128; s > 0; s >>= 1) {
        if (t < s) sm[t] += sm[t + s];
        __syncthreads();
    }
    if (t == 0) g_dis[j] = rsqrtf(1.0f + sm[0]);
}

// ---------------- scorer matvecs: u = x@Wn, v = x@Wr ----------------
__global__ void k_scorevec(const float* __restrict__ x,
                           const float* __restrict__ Wn,
                           const float* __restrict__ Wr) {
    int j = blockIdx.x, t = threadIdx.x;  // 256 threads
    float p = x[(size_t)j * H + t];
    float uu = p * Wn[t], vv = p * Wr[t];
    __shared__ float su[256], sv[256];
    su[t] = uu; sv[t] = vv; __syncthreads();
    for (int s = 128; s > 0; s >>= 1) {
        if (t < s) { su[t] += su[t + s]; sv[t] += sv[t + s]; }
        __syncthreads();
    }
    if (t == 0) { g_u[j] = su[0]; g_v[j] = sv[0]; }
}

// ---------------- w = A@u (A strictly lower), score = tanh(w + bs + v) ----------------
__global__ void k_auscore(const float* __restrict__ Aadj,
                          const float* __restrict__ bsp, int Nl) {
    int j = blockIdx.x, t = threadIdx.x;
    const float* row = Aadj + (size_t)j * Nl;
    float s = 0.0f;
    for (int i = t; i < j; i += 256) s += row[i] * g_u[i];
    __shared__ float sm[256];
    sm[t] = s; __syncthreads();
    for (int st = 128; st > 0; st >>= 1) {
        if (t < st) sm[t] += sm[t + st];
        __syncthreads();
    }
    if (t == 0) g_score[j] = tanhf(sm[0] + bsp[0] + g_v[j]);
}

// ---------------- top-k via bitonic sort (1 block, 1024 threads, P=4096) ----------------
__device__ void bitonic4096(float* ss, int* si, bool byScore) {
    int t = threadIdx.x;
    for (int size = 2; size <= 4096; size <<= 1) {
        for (int stride = size >> 1; stride > 0; stride >>= 1) {
            __syncthreads();
            for (int p = t; p < 2048; p += 1024) {
                int i = ((p / stride) * (stride << 1)) + (p % stride);
                int j = i + stride;
                bool dirUp = ((i & size) == 0);
                float sa = ss[i], sb = ss[j];
                int ia = si[i], ib = si[j];
                // b true if j-element precedes i-element in target order
                bool b = byScore ? ((sb > sa) || (sb == sa && ib < ia)) : (ib < ia);
                if (b == dirUp) {
                    ss[i] = sb; ss[j] = sa;
                    si[i] = ib; si[j] = ia;
                }
            }
        }
    }
    __syncthreads();
}

__global__ __launch_bounds__(1024) void k_topk(int Nl, int k) {
    __shared__ float ss[4096];
    __shared__ int   si[4096];
    int t = threadIdx.x;
    for (int i = t; i < 4096; i += 1024) {
        if (i < Nl) { ss[i] = g_score[i]; si[i] = i; }
        else        { ss[i] = __int_as_float(0xff800000); si[i] = 0x7FFFFFFF; }
    }
    __syncthreads();
    // phase 1: descending by score (tie -> smaller index), matches lax.top_k set
    bitonic4096(ss, si, true);
    // phase 2: keep first k, re-sort selected by index ascending (keeps A triangular)
    for (int i = t; i < 4096; i += 1024)
        if (i >= k) si[i] = 0x7FFFFFFF;
    __syncthreads();
    bitonic4096(ss, si, false);
    for (int r = t; r < k; r += 1024) { g_perm[r] = si[r]; g_vals[r] = ss[r]; }
}

// ---------------- gather x: xp[r] = x[perm[r]] * vals[r] ----------------
__global__ void k_gatherx(const float* __restrict__ xin, float* __restrict__ xout, int k) {
    int r = blockIdx.x, t = threadIdx.x;
    int pr = g_perm[r];
    float v = g_vals[r];
    xout[(size_t)r * H + t] = xin[(size_t)pr * H + t] * v;
}

// ---------------- gather A (stays strictly lower) + new degrees ----------------
__global__ void k_gatherA(const float* __restrict__ Ain, float* __restrict__ Aout,
                          int Nin, int k) {
    int r = blockIdx.x, t = threadIdx.x;
    int pr = g_perm[r];
    const float* rin = Ain + (size_t)pr * Nin;
    float* rout = Aout + (size_t)r * k;
    float cnt = 0.0f;
    for (int c = t; c < k; c += 256) {
        float a = (c < r) ? rin[g_perm[c]] : 0.0f;
        rout[c] = a;
        cnt += a;
    }
    __shared__ float sm[256];
    sm[t] = cnt; __syncthreads();
    for (int s = 128; s > 0; s >>= 1) {
        if (t < s) sm[t] += sm[t + s];
        __syncthreads();
    }
    if (t == 0) g_dis[r] = rsqrtf(1.0f + sm[0]);
}

// ---------------- readout: column max + sum -> accumulate into out ----------------
__global__ void k_readout_part(const float* __restrict__ x, int k) {
    int b = blockIdx.x, t = threadIdx.x;  // grid 32, 256 threads
    float mx = __int_as_float(0xff800000), sm = 0.0f;
    for (int r = b; r < k; r += 32) {
        float v = x[(size_t)r * H + t];
        mx = fmaxf(mx, v);
        sm += v;
    }
    g_part[b * 512 + t] = mx;
    g_part[b * 512 + 256 + t] = sm;
}

__global__ void k_readout_final(float* out, float invk) {
    int t = threadIdx.x;  // 256
    float mx = __int_as_float(0xff800000), sm = 0.0f;
    for (int b = 0; b < 32; b++) {
        mx = fmaxf(mx, g_part[b * 512 + t]);
        sm += g_part[b * 512 + 256 + t];
    }
    out[t] += mx;
    out[256 + t] += sm * invk;
}

// ---------------- one GCN + SAGPool + readout layer ----------------
static void run_layer(const float* xin, int Kin, const float* Ain, int Nl,
                      const float* W, const float* bvec,
                      const float* Wr, const float* Wn, const float* bs,
                      int k, float* xnew, float* xpool, float* Apool,
                      float* ybuf, const float* pdis, float* d_out)
{
    // y = dis .* (x @ W)
    {
        dim3 g(H / 128, Nl / 128);
        k_sgemm<1, false, false, false><<<g, 256>>>(xin, W, ybuf, Nl, H, Kin,
                                                    pdis, nullptr, nullptr);
    }
    // xnew = relu(dis .* (A@y + y) + b)   [A strictly lower -> TRI K-limit]
    {
        dim3 g(H / 128, Nl / 128);
        k_sgemm<2, false, false, true><<<g, 256>>>(Ain, ybuf, xnew, Nl, H, Nl,
                                                   pdis, ybuf, bvec);
    }
    k_scorevec<<<Nl, 256>>>(xnew, Wn, Wr);
    k_auscore<<<Nl, 256>>>(Ain, bs, Nl);
    k_topk<<<1, 1024>>>(Nl, k);
    k_gatherx<<<k, 256>>>(xnew, xpool, k);
    k_gatherA<<<k, 256>>>(Ain, Apool, Nl, k);
    k_readout_part<<<32, 256>>>(xpool, k);
    k_readout_final<<<1, 256>>>(d_out, 1.0f / (float)k);
}

extern "C" void kernel_launch(void* const* d_in, const int* in_sizes, int n_in,
                              void* d_out, int out_size) {
    const float* feature = (const float*)d_in[0];
    const float* img     = (const float*)d_in[1];
    const float* W_pos   = (const float*)d_in[2];
    const float* b_pos   = (const float*)d_in[3];
    const float* W1 = (const float*)d_in[4];  const float* b1 = (const float*)d_in[5];
    const float* W2 = (const float*)d_in[6];  const float* b2 = (const float*)d_in[7];
    const float* W3 = (const float*)d_in[8];  const float* b3 = (const float*)d_in[9];
    const float* Wr1 = (const float*)d_in[10]; const float* Wn1 = (const float*)d_in[11];
    const float* bs1 = (const float*)d_in[12];
    const float* Wr2 = (const float*)d_in[13]; const float* Wn2 = (const float*)d_in[14];
    const float* bs2 = (const float*)d_in[15];
    const float* Wr3 = (const float*)d_in[16]; const float* Wn3 = (const float*)d_in[17];
    const float* bs3 = (const float*)d_in[18];
    float* out = (float*)d_out;

    float *pfeat, *pA, *pA2, *px, *px2, *py, *pdis;
    cudaGetSymbolAddress((void**)&pfeat, g_feat);
    cudaGetSymbolAddress((void**)&pA,   g_A);
    cudaGetSymbolAddress((void**)&pA2,  g_A2);
    cudaGetSymbolAddress((void**)&px,   g_x);
    cudaGetSymbolAddress((void**)&px2,  g_x2);
    cudaGetSymbolAddress((void**)&py,   g_y);
    cudaGetSymbolAddress((void**)&pdis, g_dis);   // FIX: device address, not host shadow

    k_init<<<2, 256>>>(out);
    k_posconcat<<<N0, 128>>>(feature, img, W_pos, b_pos);

    // Gram (lower triangle + diagonal only): G = feat @ feat^T into g_A
    {
        dim3 g(N0 / 128, N0 / 128);
        k_sgemm<0, true, true, false><<<g, 256>>>(pfeat, pfeat, pA, N0, N0, F0,
                                                  nullptr, nullptr, nullptr);
    }
    k_diag<<<N0 / 256, 256>>>();
    k_maxd2<<<N0, 256>>>();
    k_buildadj<<<N0, 256>>>();

    // layer 1: A in g_A (4096), pool -> x2 (3072), A -> g_A2
    run_layer(pfeat, F0, pA, N0, W1, b1, Wr1, Wn1, bs1, KP1, px, px2, pA2, py, pdis, out);
    // layer 2: A in g_A2 (3072), pool -> x2 (2304), A -> g_A
    run_layer(px2, H, pA2, KP1, W2, b2, Wr2, Wn2, bs2, KP2, px, px2, pA, py, pdis, out);
    // layer 3: A in g_A (2304), pool -> x2 (1728), A -> g_A2
    run_layer(px2, H, pA, KP2, W3, b3, Wr3, Wn3, bs3, KP3, px, px2, pA2, py, pdis, out);
}

// round 9
// speedup vs baseline: 1.0035x; 1.0029x over previous
#include <cuda_runtime.h>
#include <math.h>

#define N0 4096
#define F0 512
#define H  256
#define KP1 3072
#define KP2 2304
#define KP3 1728

// ---------------- device scratch (static globals: no runtime allocation) ----------------
__device__ __align__(256) float g_feat[N0 * F0];
__device__ __align__(256) float g_A [(size_t)N0 * N0];
__device__ __align__(256) float g_A2[(size_t)N0 * N0];
__device__ __align__(256) float g_x [N0 * H];
__device__ __align__(256) float g_x2[N0 * H];
__device__ __align__(256) float g_y [N0 * H];
__device__ float g_sq[N0];
__device__ float g_dis[N0];
__device__ float g_u[N0];
__device__ float g_v[N0];
__device__ float g_score[N0];
__device__ int   g_perm[N0];
__device__ float g_vals[N0];
__device__ int   g_maxint;
__device__ float g_part[32 * 512];

// ---------------- init ----------------
__global__ void k_init(float* out) {
    int t = blockIdx.x * blockDim.x + threadIdx.x;
    if (t < 512) out[t] = 0.0f;
    if (t == 0) g_maxint = 0;
}

// ---------------- pos MLP + concat -> feat [N0, 512] ----------------
__global__ void k_posconcat(const float* __restrict__ feature,
                            const float* __restrict__ img,
                            const float* __restrict__ Wp,
                            const float* __restrict__ bp) {
    int n = blockIdx.x;
    int t = threadIdx.x;  // 128 threads
    const float* fr = feature + (size_t)n * 500;
    float* dst = g_feat + (size_t)n * F0;
    for (int i = t; i < 500; i += 128) dst[i] = fr[i];
    if (t < 12) {
        float s = bp[t];
#pragma unroll
        for (int h = 0; h < 6; h++) s += img[n * 6 + h] * Wp[h * 12 + t];
        dst[500 + t] = fmaxf(s, 0.0f);
    }
}

// ---------------- SGEMM: C[M,N] = A[M,K] @ B (BT: B is [N,K] row-major) ----------------
// EPI 0: plain store
// EPI 1: C = dis[m] * acc                         (y = dis .* (x@W))
// EPI 2: C = relu(dis[m]*(acc + ybuf[m,n]) + bias[n])   (GCN with self loop)
// LOWER: skip blocks above diagonal (Gram lower triangle only)
// TRI:   A operand strictly lower triangular -> K loop limited to m0+128
template<int EPI, bool BT, bool LOWER, bool TRI>
__global__ __launch_bounds__(256) void k_sgemm(
    const float* __restrict__ A, const float* __restrict__ B, float* __restrict__ C,
    int M, int N, int K,
    const float* __restrict__ dis, const float* __restrict__ ybuf,
    const float* __restrict__ bias)
{
    int bx = blockIdx.x, by = blockIdx.y;
    if (LOWER && bx > by) return;
    int m0 = by * 128, n0 = bx * 128;
    int Kend = TRI ? min(K, m0 + 128) : K;

    __shared__ float As[8][128];
    __shared__ float Bs[8][128];

    int tid = threadIdx.x;
    int trow = tid >> 4, tcol = tid & 15;
    float acc[8][8];
#pragma unroll
    for (int i = 0; i < 8; i++)
#pragma unroll
        for (int j = 0; j < 8; j++) acc[i][j] = 0.0f;

    int ar = tid >> 1, ac = (tid & 1) * 4;
    int brn = tid >> 5, bcn = (tid & 31) * 4;

    for (int k0 = 0; k0 < Kend; k0 += 8) {
        float4 av = *(const float4*)(A + (size_t)(m0 + ar) * K + k0 + ac);
        As[ac + 0][ar] = av.x; As[ac + 1][ar] = av.y;
        As[ac + 2][ar] = av.z; As[ac + 3][ar] = av.w;
        if (!BT) {
            float4 bv = *(const float4*)(B + (size_t)(k0 + brn) * N + n0 + bcn);
            *(float4*)&Bs[brn][bcn] = bv;
        } else {
            float4 bv = *(const float4*)(B + (size_t)(n0 + ar) * K + k0 + ac);
            Bs[ac + 0][ar] = bv.x; Bs[ac + 1][ar] = bv.y;
            Bs[ac + 2][ar] = bv.z; Bs[ac + 3][ar] = bv.w;
        }
        __syncthreads();
#pragma unroll
        for (int kk = 0; kk < 8; kk++) {
            float ra[8], rb[8];
#pragma unroll
            for (int i = 0; i < 8; i++) ra[i] = As[kk][trow * 8 + i];
#pragma unroll
            for (int j = 0; j < 8; j++) rb[j] = Bs[kk][tcol * 8 + j];
#pragma unroll
            for (int i = 0; i < 8; i++)
#pragma unroll
                for (int j = 0; j < 8; j++)
                    acc[i][j] = fmaf(ra[i], rb[j], acc[i][j]);
        }
        __syncthreads();
    }

#pragma unroll
    for (int i = 0; i < 8; i++) {
        int m = m0 + trow * 8 + i;
        float d = (EPI >= 1) ? dis[m] : 0.0f;
#pragma unroll
        for (int j = 0; j < 8; j++) {
            int n = n0 + tcol * 8 + j;
            float v = acc[i][j];
            if (EPI == 1) v = d * v;
            else if (EPI == 2) {
                v = d * (v + ybuf[(size_t)m * N + n]) + bias[n];
                v = fmaxf(v, 0.0f);
            }
            C[(size_t)m * N + n] = v;
        }
    }
}

// ---------------- diag of Gram = ||x||^2 ----------------
__global__ void k_diag() {
    int i = blockIdx.x * blockDim.x + threadIdx.x;
    if (i < N0) g_sq[i] = g_A[(size_t)i * N0 + i];
}

// ---------------- max d2 over lower triangle ----------------
__global__ void k_maxd2() {
    int j = blockIdx.x, t = threadIdx.x;
    float sj = g_sq[j];
    const float* row = g_A + (size_t)j * N0;
    float m = 0.0f;
    for (int i = t; i <= j; i += 256) {
        float d2 = sj + g_sq[i] - 2.0f * row[i];
        m = fmaxf(m, d2);
    }
    __shared__ float sm[256];
    sm[t] = m; __syncthreads();
    for (int s = 128; s > 0; s >>= 1) {
        if (t < s) sm[t] = fmaxf(sm[t], sm[t + s]);
        __syncthreads();
    }
    if (t == 0) atomicMax(&g_maxint, __float_as_int(fmaxf(sm[0], 0.0f)));
}

// ---------------- build adjacency in place + degree -> dis ----------------
__global__ void k_buildadj() {
    int j = blockIdx.x, t = threadIdx.x;
    float thr = 0.5f * __int_as_float(g_maxint);
    float sj = g_sq[j];
    float* row = g_A + (size_t)j * N0;
    float cnt = 0.0f;
    for (int i = t; i < N0; i += 256) {
        float a = 0.0f;
        if (i < j) {
            float d2 = sj + g_sq[i] - 2.0f * row[i];
            a = (d2 < thr) ? 1.0f : 0.0f;
        }
        row[i] = a;
        cnt += a;
    }
    __shared__ float sm[256];
    sm[t] = cnt; __syncthreads();
    for (int s = 128; s > 0; s >>= 1) {
        if (t < s) sm[t] += sm[t + s];
        __syncthreads();
    }
    if (t == 0) g_dis[j] = rsqrtf(1.0f + sm[0]);
}

// ---------------- scorer matvecs: u = x@Wn, v = x@Wr ----------------
__global__ void k_scorevec(const float* __restrict__ x,
                           const float* __restrict__ Wn,
                           const float* __restrict__ Wr) {
    int j = blockIdx.x, t = threadIdx.x;  // 256 threads
    float p = x[(size_t)j * H + t];
    float uu = p * Wn[t], vv = p * Wr[t];
    __shared__ float su[256], sv[256];
    su[t] = uu; sv[t] = vv; __syncthreads();
    for (int s = 128; s > 0; s >>= 1) {
        if (t < s) { su[t] += su[t + s]; sv[t] += sv[t + s]; }
        __syncthreads();
    }
    if (t == 0) { g_u[j] = su[0]; g_v[j] = sv[0]; }
}

// ---------------- w = A@u (A strictly lower), score = tanh(w + bs + v) ----------------
__global__ void k_auscore(const float* __restrict__ Aadj,
                          const float* __restrict__ bsp, int Nl) {
    int j = blockIdx.x, t = threadIdx.x;
    const float* row = Aadj + (size_t)j * Nl;
    float s = 0.0f;
    for (int i = t; i < j; i += 256) s += row[i] * g_u[i];
    __shared__ float sm[256];
    sm[t] = s; __syncthreads();
    for (int st = 128; st > 0; st >>= 1) {
        if (t < st) sm[t] += sm[t + st];
        __syncthreads();
    }
    if (t == 0) g_score[j] = tanhf(sm[0] + bsp[0] + g_v[j]);
}

// ---------------- top-k via bitonic sort (1 block, 1024 threads, P=4096) ----------------
__device__ void bitonic4096(float* ss, int* si, bool byScore) {
    int t = threadIdx.x;
    for (int size = 2; size <= 4096; size <<= 1) {
        for (int stride = size >> 1; stride > 0; stride >>= 1) {
            __syncthreads();
            for (int p = t; p < 2048; p += 1024) {
                int i = ((p / stride) * (stride << 1)) + (p % stride);
                int j = i + stride;
                bool dirUp = ((i & size) == 0);
                float sa = ss[i], sb = ss[j];
                int ia = si[i], ib = si[j];
                // b true if j-element precedes i-element in target order
                bool b = byScore ? ((sb > sa) || (sb == sa && ib < ia)) : (ib < ia);
                if (b == dirUp) {
                    ss[i] = sb; ss[j] = sa;
                    si[i] = ib; si[j] = ia;
                }
            }
        }
    }
    __syncthreads();
}

__global__ __launch_bounds__(1024) void k_topk(int Nl, int k) {
    __shared__ float ss[4096];
    __shared__ int   si[4096];
    int t = threadIdx.x;
    for (int i = t; i < 4096; i += 1024) {
        if (i < Nl) { ss[i] = g_score[i]; si[i] = i; }
        else        { ss[i] = __int_as_float(0xff800000); si[i] = 0x7FFFFFFF; }
    }
    __syncthreads();
    // phase 1: descending by score (tie -> smaller index), matches lax.top_k set
    bitonic4096(ss, si, true);
    // phase 2: keep first k, re-sort selected by index ascending (keeps A triangular)
    for (int i = t; i < 4096; i += 1024)
        if (i >= k) si[i] = 0x7FFFFFFF;
    __syncthreads();
    bitonic4096(ss, si, false);
    for (int r = t; r < k; r += 1024) { g_perm[r] = si[r]; g_vals[r] = ss[r]; }
}

// ---------------- gather x: xp[r] = x[perm[r]] * vals[r] ----------------
__global__ void k_gatherx(const float* __restrict__ xin, float* __restrict__ xout, int k) {
    int r = blockIdx.x, t = threadIdx.x;
    int pr = g_perm[r];
    float v = g_vals[r];
    xout[(size_t)r * H + t] = xin[(size_t)pr * H + t] * v;
}

// ---------------- gather A (stays strictly lower) + new degrees ----------------
__global__ void k_gatherA(const float* __restrict__ Ain, float* __restrict__ Aout,
                          int Nin, int k) {
    int r = blockIdx.x, t = threadIdx.x;
    int pr = g_perm[r];
    const float* rin = Ain + (size_t)pr * Nin;
    float* rout = Aout + (size_t)r * k;
    float cnt = 0.0f;
    for (int c = t; c < k; c += 256) {
        float a = (c < r) ? rin[g_perm[c]] : 0.0f;
        rout[c] = a;
        cnt += a;
    }
    __shared__ float sm[256];
    sm[t] = cnt; __syncthreads();
    for (int s = 128; s > 0; s >>= 1) {
        if (t < s) sm[t] += sm[t + s];
        __syncthreads();
    }
    if (t == 0) g_dis[r] = rsqrtf(1.0f + sm[0]);
}

// ---------------- readout: column max + sum -> accumulate into out ----------------
__global__ void k_readout_part(const float* __restrict__ x, int k) {
    int b = blockIdx.x, t = threadIdx.x;  // grid 32, 256 threads
    float mx = __int_as_float(0xff800000), sm = 0.0f;
    for (int r = b; r < k; r += 32) {
        float v = x[(size_t)r * H + t];
        mx = fmaxf(mx, v);
        sm += v;
    }
    g_part[b * 512 + t] = mx;
    g_part[b * 512 + 256 + t] = sm;
}

__global__ void k_readout_final(float* out, float invk) {
    int t = threadIdx.x;  // 256
    float mx = __int_as_float(0xff800000), sm = 0.0f;
    for (int b = 0; b < 32; b++) {
        mx = fmaxf(mx, g_part[b * 512 + t]);
        sm += g_part[b * 512 + 256 + t];
    }
    out[t] += mx;
    out[256 + t] += sm * invk;
}

// ---------------- one GCN + SAGPool + readout layer ----------------
static void run_layer(const float* xin, int Kin, const float* Ain, int Nl,
                      const float* W, const float* bvec,
                      const float* Wr, const float* Wn, const float* bs,
                      int k, float* xnew, float* xpool, float* Apool,
                      float* ybuf, const float* pdis, float* d_out)
{
    // y = dis .* (x @ W)
    {
        dim3 g(H / 128, Nl / 128);
        k_sgemm<1, false, false, false><<<g, 256>>>(xin, W, ybuf, Nl, H, Kin,
                                                    pdis, nullptr, nullptr);
    }
    // xnew = relu(dis .* (A@y + y) + b)   [A strictly lower -> TRI K-limit]
    {
        dim3 g(H / 128, Nl / 128);
        k_sgemm<2, false, false, true><<<g, 256>>>(Ain, ybuf, xnew, Nl, H, Nl,
                                                   pdis, ybuf, bvec);
    }
    k_scorevec<<<Nl, 256>>>(xnew, Wn, Wr);
    k_auscore<<<Nl, 256>>>(Ain, bs, Nl);
    k_topk<<<1, 1024>>>(Nl, k);
    k_gatherx<<<k, 256>>>(xnew, xpool, k);
    k_gatherA<<<k, 256>>>(Ain, Apool, Nl, k);
    k_readout_part<<<32, 256>>>(xpool, k);
    k_readout_final<<<1, 256>>>(d_out, 1.0f / (float)k);
}

extern "C" void kernel_launch(void* const* d_in, const int* in_sizes, int n_in,
                              void* d_out, int out_size) {
    const float* feature = (const float*)d_in[0];
    const float* img     = (const float*)d_in[1];
    const float* W_pos   = (const float*)d_in[2];
    const float* b_pos   = (const float*)d_in[3];
    const float* W1 = (const float*)d_in[4];  const float* b1 = (const float*)d_in[5];
    const float* W2 = (const float*)d_in[6];  const float* b2 = (const float*)d_in[7];
    const float* W3 = (const float*)d_in[8];  const float* b3 = (const float*)d_in[9];
    const float* Wr1 = (const float*)d_in[10]; const float* Wn1 = (const float*)d_in[11];
    const float* bs1 = (const float*)d_in[12];
    const float* Wr2 = (const float*)d_in[13]; const float* Wn2 = (const float*)d_in[14];
    const float* bs2 = (const float*)d_in[15];
    const float* Wr3 = (const float*)d_in[16]; const float* Wn3 = (const float*)d_in[17];
    const float* bs3 = (const float*)d_in[18];
    float* out = (float*)d_out;

    float *pfeat, *pA, *pA2, *px, *px2, *py, *pdis;
    cudaGetSymbolAddress((void**)&pfeat, g_feat);
    cudaGetSymbolAddress((void**)&pA,   g_A);
    cudaGetSymbolAddress((void**)&pA2,  g_A2);
    cudaGetSymbolAddress((void**)&px,   g_x);
    cudaGetSymbolAddress((void**)&px2,  g_x2);
    cudaGetSymbolAddress((void**)&py,   g_y);
    cudaGetSymbolAddress((void**)&pdis, g_dis);   // FIX: device address, not host shadow

    k_init<<<2, 256>>>(out);
    k_posconcat<<<N0, 128>>>(feature, img, W_pos, b_pos);

    // Gram (lower triangle + diagonal only): G = feat @ feat^T into g_A
    {
        dim3 g(N0 / 128, N0 / 128);
        k_sgemm<0, true, true, false><<<g, 256>>>(pfeat, pfeat, pA, N0, N0, F0,
                                                  nullptr, nullptr, nullptr);
    }
    k_diag<<<N0 / 256, 256>>>();
    k_maxd2<<<N0, 256>>>();
    k_buildadj<<<N0, 256>>>();

    // layer 1: A in g_A (4096), pool -> x2 (3072), A -> g_A2
    run_layer(pfeat, F0, pA, N0, W1, b1, Wr1, Wn1, bs1, KP1, px, px2, pA2, py, pdis, out);
    // layer 2: A in g_A2 (3072), pool -> x2 (2304), A -> g_A
    run_layer(px2, H, pA2, KP1, W2, b2, Wr2, Wn2, bs2, KP2, px, px2, pA, py, pdis, out);
    // layer 3: A in g_A (2304), pool -> x2 (1728), A -> g_A2
    run_layer(px2, H, pA, KP2, W3, b3, Wr3, Wn3, bs3, KP3, px, px2, pA2, py, pdis, out);
}